// round 1
// baseline (speedup 1.0000x reference)
#include <cuda_runtime.h>
#include <cuda_bf16.h>
#include <math_constants.h>

// Problem constants (from reference)
#define BQ 64
#define LQ 32
#define BD 128
#define LD 192
#define TOK_D 32
#define CLS_D 768

// Sorted (id<<8 | j) keys per doc, padded to 256 with 0xFFFFFFFF
__device__ unsigned g_skeys[BD * 256];

// ---------------------------------------------------------------------------
// Kernel 1: per-doc rank sort of (token_id << 8 | j) keys. Keys are unique
// (j in low bits), so rank = count of strictly-smaller keys.
// ---------------------------------------------------------------------------
__global__ void sort_doc_keys_kernel(const int* __restrict__ doc_ids) {
    __shared__ unsigned k[LD];
    const int d = blockIdx.x;
    const int t = threadIdx.x;  // 256 threads

    if (t < LD) {
        k[t] = ((unsigned)doc_ids[d * LD + t] << 8) | (unsigned)t;
    }
    __syncthreads();

    if (t < LD) {
        const unsigned mine = k[t];
        int rank = 0;
#pragma unroll 8
        for (int o = 0; o < LD; o++) {
            rank += (k[o] < mine) ? 1 : 0;
        }
        g_skeys[d * 256 + rank] = mine;
    } else {
        g_skeys[d * 256 + t] = 0xFFFFFFFFu;  // pad entries 192..255
    }
}

// ---------------------------------------------------------------------------
// Kernel 2: one warp per (q, d). Lane = query token position i.
//   block = (d, 8 queries), grid = (128, 8), 256 threads.
// ---------------------------------------------------------------------------
__global__ __launch_bounds__(256) void coil_score_kernel(
    const float* __restrict__ qtok,   // [BQ, LQ, TOK_D]
    const float* __restrict__ dtok,   // [BD, LD, TOK_D]
    const float* __restrict__ qcls,   // [BQ, CLS_D]
    const float* __restrict__ dcls,   // [BD, CLS_D]
    const int*   __restrict__ qids,   // [BQ, LQ]
    const int*   __restrict__ qmask,  // [BQ, LQ]
    float*       __restrict__ out)    // [BQ, BD]
{
    __shared__ unsigned skeys[256];
    const int d = blockIdx.x;
    const int t = threadIdx.x;

    skeys[t] = g_skeys[d * 256 + t];
    __syncthreads();

    const int warp = t >> 5;
    const int lane = t & 31;
    const int q = blockIdx.y * 8 + warp;

    // --- query mask with SEP zeroed: sep = sum(mask) - 1 ---
    const int mv = qmask[q * LQ + lane];
    int tot = mv;
#pragma unroll
    for (int s = 16; s; s >>= 1) tot += __shfl_xor_sync(0xFFFFFFFFu, tot, s);
    const float qmf = (lane == tot - 1) ? 0.0f : (float)mv;

    // --- token-match max over doc positions ---
    const int qid = qids[q * LQ + lane];
    const unsigned target = (unsigned)qid << 8;

    // branchless lower_bound over 256 sorted keys (pad guarantees bound <= 192)
    int idx = 0;
#pragma unroll
    for (int s = 128; s; s >>= 1) {
        if (skeys[idx + s - 1] < target) idx += s;
    }

    float m = -CUDART_INF_F;
    int nmatch = 0;
    const float4* qe = (const float4*)(qtok + (q * LQ + lane) * TOK_D);
    while (idx < LD) {
        const unsigned key = skeys[idx];
        if ((key >> 8) != (unsigned)qid) break;
        const int j = (int)(key & 0xFFu);
        const float4* de = (const float4*)(dtok + (d * LD + j) * TOK_D);
        float s0 = 0.0f;
#pragma unroll
        for (int e = 0; e < TOK_D / 4; e++) {
            const float4 a = qe[e];
            const float4 b = de[e];
            s0 += a.x * b.x + a.y * b.y + a.z * b.z + a.w * b.w;
        }
        m = fmaxf(m, s0);
        nmatch++;
        idx++;
    }
    // where(match, score, 0).max(-1): zeros participate iff any non-match exists
    if (nmatch < LD) m = fmaxf(m, 0.0f);

    // drop CLS position (i==0), apply mask weight
    float total = (lane >= 1) ? m * qmf : 0.0f;

    // --- CLS GEMM contribution: dot(qcls[q], dcls[d]) split across lanes ---
    const float4* qc = (const float4*)(qcls + q * CLS_D);
    const float4* dc = (const float4*)(dcls + d * CLS_D);
#pragma unroll
    for (int tt = 0; tt < CLS_D / (4 * 32); tt++) {
        const float4 a = qc[lane + 32 * tt];
        const float4 b = dc[lane + 32 * tt];
        total += a.x * b.x + a.y * b.y + a.z * b.z + a.w * b.w;
    }

    // --- warp reduction, lane 0 writes ---
#pragma unroll
    for (int s = 16; s; s >>= 1) total += __shfl_xor_sync(0xFFFFFFFFu, total, s);
    if (lane == 0) out[q * BD + d] = total;
}

// ---------------------------------------------------------------------------
// Launch
// ---------------------------------------------------------------------------
extern "C" void kernel_launch(void* const* d_in, const int* in_sizes, int n_in,
                              void* d_out, int out_size) {
    const float* qtok  = (const float*)d_in[0];  // query_tok_embs [64,32,32]
    const float* dtok  = (const float*)d_in[1];  // doc_tok_embs   [128,192,32]
    const float* qcls  = (const float*)d_in[2];  // query_cls_emb  [64,768]
    const float* dcls  = (const float*)d_in[3];  // doc_cls_emb    [128,768]
    const int*   qids  = (const int*)d_in[4];    // query_input_ids [64,32]
    const int*   dids  = (const int*)d_in[5];    // doc_input_ids   [128,192]
    const int*   qmask = (const int*)d_in[6];    // query_attention_mask [64,32]
    float* out = (float*)d_out;                  // [64,128]

    sort_doc_keys_kernel<<<BD, 256>>>(dids);
    dim3 grid(BD, BQ / 8);
    coil_score_kernel<<<grid, 256>>>(qtok, dtok, qcls, dcls, qids, qmask, out);
}